// round 1
// baseline (speedup 1.0000x reference)
#include <cuda_runtime.h>
#include <math.h>

#define B_      8
#define IN_CH   512
#define OUT_CH  256
#define HW      64
#define OH      129   // conv-transpose output spatial (2*64-2+3)

// ---------------- scratch (__device__ globals; no allocation allowed) ----------------
__device__ float g_style[B_ * IN_CH];
__device__ float g_demod[B_ * OUT_CH];
__device__ float g_wsqT[IN_CH * OUT_CH];                       // [i][o]
__device__ float g_wmod[(size_t)B_ * 9 * IN_CH * OUT_CH];      // [b][kh*3+kw][i][o]
__device__ float g_out1[(size_t)B_ * OUT_CH * OH * OH];        // conv-transpose result

// ---------------- 1) style = w @ (aw/sqrt(512)).T + bias ----------------
__global__ void style_kernel(const float* __restrict__ w,
                             const float* __restrict__ aw,
                             const float* __restrict__ bias) {
    int b = blockIdx.x;
    int i = threadIdx.x;               // 512 threads
    __shared__ float ws[IN_CH];
    ws[i] = w[b * IN_CH + i];
    __syncthreads();
    const float* ar = aw + (size_t)i * IN_CH;
    float s = 0.f;
#pragma unroll 8
    for (int l = 0; l < IN_CH; ++l) s = fmaf(ws[l], ar[l], s);
    g_style[b * IN_CH + i] = s * 0.04419417382415922f /* 1/sqrt(512) */ + bias[i];
}

// ---------------- 2a) wsq[i][o] = sum_k cw[o,i,k]^2 ----------------
__global__ void wsq_kernel(const float* __restrict__ cw) {
    int t = blockIdx.x * blockDim.x + threadIdx.x;   // IN_CH*OUT_CH threads
    int o = t & (OUT_CH - 1);
    int i = t >> 8;
    const float* p = cw + ((size_t)o * IN_CH + i) * 9;
    float s = 0.f;
#pragma unroll
    for (int k = 0; k < 9; ++k) s = fmaf(p[k], p[k], s);
    g_wsqT[i * OUT_CH + o] = s;
}

// ---------------- 2b) demod[b][o] ----------------
__global__ void demod_kernel() {
    int b = blockIdx.x;
    int o = threadIdx.x;               // 256 threads
    __shared__ float s2[IN_CH];
    for (int l = threadIdx.x; l < IN_CH; l += 256) {
        float v = g_style[b * IN_CH + l];
        s2[l] = v * v;
    }
    __syncthreads();
    float acc = 0.f;
#pragma unroll 4
    for (int i = 0; i < IN_CH; ++i) acc = fmaf(s2[i], g_wsqT[i * OUT_CH + o], acc);
    g_demod[b * OUT_CH + o] = rsqrtf(acc * (1.f / 4608.f) + 1e-8f);
}

// ---------------- 3) Wmod[b][k][i][o] = scale*cw*style*demod ----------------
__global__ void wmod_kernel(const float* __restrict__ cw) {
    int b = blockIdx.y;
    int e = blockIdx.x * 256 + threadIdx.x;          // < 9*512*256
    int o = e & 255;
    int i = (e >> 8) & 511;
    int k = e >> 17;                                 // 0..8
    float v = cw[((size_t)o * IN_CH + i) * 9 + k];
    float m = v * 0.014731391274719739f /* 1/sqrt(512*9) */
                * g_style[b * IN_CH + i] * g_demod[b * OUT_CH + o];
    g_wmod[(((size_t)b * 9 + k) * IN_CH + i) * OUT_CH + o] = m;
}

// ---------------- 4) conv-transpose, one kernel per output parity ----------------
// out1[2*py+RY, 2*px+RX] = sum_i sum_taps Wmod[kh,kw]*x[py+dy, px+dx]
// RY==0: (kh=0,dy=0),(kh=2,dy=-1);  RY==1: (kh=1,dy=0). Same for X.
template <int RY, int RX>
__global__ void __launch_bounds__(256) conv_kernel(const float* __restrict__ x) {
    constexpr int TY = (RY == 0) ? 2 : 1;
    constexpr int TX = (RX == 0) ? 2 : 1;
    constexpr int T  = TY * TX;
    constexpr int NY = (RY == 0) ? 65 : 64;   // number of py values (Y=2py+RY < 129)
    constexpr int NX = (RX == 0) ? 65 : 64;
    constexpr int TILESX = (NX + 7) / 8;

    __shared__ float Wsm[T][16][64];
    __shared__ float Xsm[16][9][12];

    const int b     = blockIdx.z;
    const int obase = blockIdx.y * 64;
    const int ty    = blockIdx.x / TILESX;
    const int tx    = blockIdx.x % TILESX;
    const int py0   = ty * 8;
    const int px0   = tx * 8;
    const int tid   = threadIdx.x;
    const int go    = tid >> 4;        // 16 o-groups of 4
    const int gs    = tid & 15;        // 16 spatial groups (2x2 cells)
    const int cy    = gs >> 2;
    const int cx    = gs & 3;

    float acc[4][4];
#pragma unroll
    for (int a = 0; a < 4; ++a)
#pragma unroll
        for (int s = 0; s < 4; ++s) acc[a][s] = 0.f;

    const float* xb = x + (size_t)b * IN_CH * HW * HW;

    for (int i0 = 0; i0 < IN_CH; i0 += 16) {
        // load weights: T taps x 16 ic x 64 o (coalesced)
        for (int idx = tid; idx < T * 16 * 64; idx += 256) {
            int o  = idx & 63;
            int ic = (idx >> 6) & 15;
            int t  = idx >> 10;
            int kh = (TY == 2) ? ((t / TX) ? 2 : 0) : 1;
            int kw = (TX == 2) ? ((t % TX) ? 2 : 0) : 1;
            Wsm[t][ic][o] =
                g_wmod[(((size_t)b * 9 + kh * 3 + kw) * IN_CH + i0 + ic) * OUT_CH + obase + o];
        }
        // load input tile with 1-halo (zero-filled OOB)
        for (int idx = tid; idx < 16 * 81; idx += 256) {
            int ic = idx / 81;
            int r  = (idx % 81) / 9;
            int c  = idx % 9;
            int gy = py0 - 1 + r;
            int gx = px0 - 1 + c;
            float v = 0.f;
            if ((unsigned)gy < HW && (unsigned)gx < HW)
                v = xb[((size_t)(i0 + ic) * HW + gy) * HW + gx];
            Xsm[ic][r][c] = v;
        }
        __syncthreads();

#pragma unroll
        for (int ic = 0; ic < 16; ++ic) {
            float xr[3][3];
#pragma unroll
            for (int r = 0; r < 3; ++r)
#pragma unroll
                for (int c = 0; c < 3; ++c)
                    xr[r][c] = Xsm[ic][2 * cy + r][2 * cx + c];

#pragma unroll
            for (int t = 0; t < T; ++t) {
                const int dy = (TY == 2) ? ((t / TX) ? -1 : 0) : 0;
                const int dx = (TX == 2) ? ((t % TX) ? -1 : 0) : 0;
                float4 wv = *reinterpret_cast<const float4*>(&Wsm[t][ic][go * 4]);
#pragma unroll
                for (int sy = 0; sy < 2; ++sy)
#pragma unroll
                    for (int sx = 0; sx < 2; ++sx) {
                        float xv = xr[sy + 1 + dy][sx + 1 + dx];
                        int s = sy * 2 + sx;
                        acc[0][s] = fmaf(wv.x, xv, acc[0][s]);
                        acc[1][s] = fmaf(wv.y, xv, acc[1][s]);
                        acc[2][s] = fmaf(wv.z, xv, acc[2][s]);
                        acc[3][s] = fmaf(wv.w, xv, acc[3][s]);
                    }
            }
        }
        __syncthreads();
    }

    // store: Y = 2*py + RY, X = 2*px + RX
#pragma unroll
    for (int sy = 0; sy < 2; ++sy)
#pragma unroll
        for (int sx = 0; sx < 2; ++sx) {
            int py = py0 + 2 * cy + sy;
            int px = px0 + 2 * cx + sx;
            if (py < NY && px < NX) {
                int Y = 2 * py + RY;
                int X = 2 * px + RX;
                size_t base = (((size_t)(b * OUT_CH + obase + go * 4)) * OH + Y) * OH + X;
                int s = sy * 2 + sx;
                g_out1[base]                         = acc[0][s];
                g_out1[base + (size_t)1 * OH * OH]   = acc[1][s];
                g_out1[base + (size_t)2 * OH * OH]   = acc[2][s];
                g_out1[base + (size_t)3 * OH * OH]   = acc[3][s];
            }
        }
}

// ---------------- 5) 4x4 FIR blur (pad 1,1; coeff B[s]B[t]/16, B=[1,3,3,1]) ----------------
__global__ void blur_kernel(float* __restrict__ out) {
    int bo = blockIdx.z;                         // b*256 + o
    int y0 = blockIdx.y * 16;
    int x0 = blockIdx.x * 16;
    __shared__ float sm[19][20];
    const float* src = g_out1 + (size_t)bo * OH * OH;
    int tid = threadIdx.x;
    for (int idx = tid; idx < 19 * 19; idx += 256) {
        int r = idx / 19, c = idx % 19;
        int gy = y0 - 1 + r, gx = x0 - 1 + c;
        sm[r][c] = ((unsigned)gy < OH && (unsigned)gx < OH) ? src[gy * OH + gx] : 0.f;
    }
    __syncthreads();
    int ly = tid >> 4, lx = tid & 15;
    const float cf[4] = {1.f, 3.f, 3.f, 1.f};
    float acc = 0.f;
#pragma unroll
    for (int u = 0; u < 4; ++u)
#pragma unroll
        for (int v = 0; v < 4; ++v)
            acc = fmaf(cf[u] * cf[v], sm[ly + u][lx + v], acc);
    out[(size_t)bo * 128 * 128 + (y0 + ly) * 128 + (x0 + lx)] = acc * (1.f / 16.f);
}

// ---------------- launch ----------------
extern "C" void kernel_launch(void* const* d_in, const int* in_sizes, int n_in,
                              void* d_out, int out_size) {
    const float* input = (const float*)d_in[0];
    const float* w     = (const float*)d_in[1];
    const float* aw    = (const float*)d_in[2];
    const float* bias  = (const float*)d_in[3];
    const float* cw    = (const float*)d_in[4];
    float* out = (float*)d_out;

    style_kernel<<<B_, IN_CH>>>(w, aw, bias);
    wsq_kernel<<<(IN_CH * OUT_CH) / 256, 256>>>(cw);
    demod_kernel<<<B_, OUT_CH>>>();
    wmod_kernel<<<dim3((9 * IN_CH * OUT_CH) / 256, B_), 256>>>(cw);

    conv_kernel<0, 0><<<dim3(9 * 9, 4, B_), 256>>>(input);
    conv_kernel<0, 1><<<dim3(9 * 8, 4, B_), 256>>>(input);
    conv_kernel<1, 0><<<dim3(8 * 9, 4, B_), 256>>>(input);
    conv_kernel<1, 1><<<dim3(8 * 8, 4, B_), 256>>>(input);

    blur_kernel<<<dim3(8, 8, B_ * OUT_CH), 256>>>(out);
}

// round 2
// speedup vs baseline: 1.1236x; 1.1236x over previous
#include <cuda_runtime.h>
#include <math.h>

#define B_      8
#define IN_CH   512
#define OUT_CH  256
#define HW      64
#define OH      129   // conv-transpose output spatial (2*64-2+3)

// ---------------- scratch (__device__ globals; no allocation allowed) ----------------
__device__ float g_style[B_ * IN_CH];
__device__ float g_demod[B_ * OUT_CH];
__device__ float g_wsqT[IN_CH * OUT_CH];                       // [i][o]
__device__ float g_wmod[(size_t)B_ * 9 * IN_CH * OUT_CH];      // [b][kh*3+kw][i][o]
__device__ float g_out1[(size_t)B_ * OUT_CH * OH * OH];        // conv-transpose result

// ---------------- packed f32x2 helpers ----------------
__device__ __forceinline__ unsigned long long dup2(float v) {
    unsigned long long r;
    asm("mov.b64 %0, {%1, %1};" : "=l"(r) : "f"(v));
    return r;
}
__device__ __forceinline__ void ffma2(unsigned long long& acc,
                                      unsigned long long a,
                                      unsigned long long b) {
    asm("fma.rn.f32x2 %0, %1, %2, %0;" : "+l"(acc) : "l"(a), "l"(b));
}
__device__ __forceinline__ void unpack2(unsigned long long p, float& lo, float& hi) {
    asm("mov.b64 {%0, %1}, %2;" : "=f"(lo), "=f"(hi) : "l"(p));
}

// ---------------- 1) style = w @ (aw/sqrt(512)).T + bias ----------------
__global__ void style_kernel(const float* __restrict__ w,
                             const float* __restrict__ aw,
                             const float* __restrict__ bias) {
    int b = blockIdx.x;
    int i = threadIdx.x;               // 512 threads
    __shared__ float ws[IN_CH];
    ws[i] = w[b * IN_CH + i];
    __syncthreads();
    const float* ar = aw + (size_t)i * IN_CH;
    float s = 0.f;
#pragma unroll 8
    for (int l = 0; l < IN_CH; ++l) s = fmaf(ws[l], ar[l], s);
    g_style[b * IN_CH + i] = s * 0.04419417382415922f /* 1/sqrt(512) */ + bias[i];
}

// ---------------- 2a) wsq[i][o] = sum_k cw[o,i,k]^2 ----------------
__global__ void wsq_kernel(const float* __restrict__ cw) {
    int t = blockIdx.x * blockDim.x + threadIdx.x;   // IN_CH*OUT_CH threads
    int o = t & (OUT_CH - 1);
    int i = t >> 8;
    const float* p = cw + ((size_t)o * IN_CH + i) * 9;
    float s = 0.f;
#pragma unroll
    for (int k = 0; k < 9; ++k) s = fmaf(p[k], p[k], s);
    g_wsqT[i * OUT_CH + o] = s;
}

// ---------------- 2b) demod[b][o] ----------------
__global__ void demod_kernel() {
    int b = blockIdx.x;
    int o = threadIdx.x;               // 256 threads
    __shared__ float s2[IN_CH];
    for (int l = threadIdx.x; l < IN_CH; l += 256) {
        float v = g_style[b * IN_CH + l];
        s2[l] = v * v;
    }
    __syncthreads();
    float acc = 0.f;
#pragma unroll 4
    for (int i = 0; i < IN_CH; ++i) acc = fmaf(s2[i], g_wsqT[i * OUT_CH + o], acc);
    g_demod[b * OUT_CH + o] = rsqrtf(acc * (1.f / 4608.f) + 1e-8f);
}

// ---------------- 3) Wmod[b][k][i][o] = scale*cw*style*demod ----------------
__global__ void wmod_kernel(const float* __restrict__ cw) {
    int b = blockIdx.y;
    int e = blockIdx.x * 256 + threadIdx.x;          // < 9*512*256
    int o = e & 255;
    int i = (e >> 8) & 511;
    int k = e >> 17;                                 // 0..8
    float v = cw[((size_t)o * IN_CH + i) * 9 + k];
    float m = v * 0.014731391274719739f /* 1/sqrt(512*9) */
                * g_style[b * IN_CH + i] * g_demod[b * OUT_CH + o];
    g_wmod[(((size_t)b * 9 + k) * IN_CH + i) * OUT_CH + o] = m;
}

// ---------------- 4) conv-transpose, one kernel per output parity ----------------
// out1[2*py+RY, 2*px+RX] = sum_i sum_taps Wmod[kh,kw]*x[py+dy, px+dx]
// RY==0: (kh=0,dy=0),(kh=2,dy=-1);  RY==1: (kh=1,dy=0). Same for X.
template <int RY, int RX>
__global__ void __launch_bounds__(256) conv_kernel(const float* __restrict__ x) {
    constexpr int TY = (RY == 0) ? 2 : 1;
    constexpr int TX = (RX == 0) ? 2 : 1;
    constexpr int T  = TY * TX;
    constexpr int NY = (RY == 0) ? 65 : 64;   // number of py values (Y=2py+RY < 129)
    constexpr int NX = (RX == 0) ? 65 : 64;
    constexpr int TILESX = (NX + 7) / 8;
    constexpr int RLO = (RY == 0) ? 0 : 1;    // xd rows actually used
    constexpr int CLO = (RX == 0) ? 0 : 1;    // xd cols actually used

    __shared__ float Wsm[T][16][64];
    __shared__ float Xsm[16][9][12];

    const int b     = blockIdx.z;
    const int obase = blockIdx.y * 64;
    const int ty    = blockIdx.x / TILESX;
    const int tx    = blockIdx.x % TILESX;
    const int py0   = ty * 8;
    const int px0   = tx * 8;
    const int tid   = threadIdx.x;
    const int go    = tid >> 4;        // 16 o-groups of 4
    const int gs    = tid & 15;        // 16 spatial groups (2x2 cells)
    const int cy    = gs >> 2;
    const int cx    = gs & 3;

    // acc[p][s]: p = packed output-channel pair (o pair 0: go*4+{0,1}; pair 1: go*4+{2,3})
    unsigned long long acc[2][4];
#pragma unroll
    for (int a = 0; a < 2; ++a)
#pragma unroll
        for (int s = 0; s < 4; ++s) acc[a][s] = 0ull;

    const float* xb = x + (size_t)b * IN_CH * HW * HW;

    for (int i0 = 0; i0 < IN_CH; i0 += 16) {
        // load weights: T taps x 16 ic x 64 o (coalesced)
        for (int idx = tid; idx < T * 16 * 64; idx += 256) {
            int o  = idx & 63;
            int ic = (idx >> 6) & 15;
            int t  = idx >> 10;
            int kh = (TY == 2) ? ((t / TX) ? 2 : 0) : 1;
            int kw = (TX == 2) ? ((t % TX) ? 2 : 0) : 1;
            Wsm[t][ic][o] =
                g_wmod[(((size_t)b * 9 + kh * 3 + kw) * IN_CH + i0 + ic) * OUT_CH + obase + o];
        }
        // load input tile with 1-halo (zero-filled OOB)
        for (int idx = tid; idx < 16 * 81; idx += 256) {
            int ic = idx / 81;
            int r  = (idx % 81) / 9;
            int c  = idx % 9;
            int gy = py0 - 1 + r;
            int gx = px0 - 1 + c;
            float v = 0.f;
            if ((unsigned)gy < HW && (unsigned)gx < HW)
                v = xb[((size_t)(i0 + ic) * HW + gy) * HW + gx];
            Xsm[ic][r][c] = v;
        }
        __syncthreads();

#pragma unroll
        for (int ic = 0; ic < 16; ++ic) {
            // duplicate the needed x values into packed (v,v) b64 registers
            unsigned long long xd[3][3];
#pragma unroll
            for (int r = RLO; r < 3; ++r)
#pragma unroll
                for (int c = CLO; c < 3; ++c)
                    xd[r][c] = dup2(Xsm[ic][2 * cy + r][2 * cx + c]);

#pragma unroll
            for (int t = 0; t < T; ++t) {
                const int dy = (TY == 2) ? ((t / TX) ? -1 : 0) : 0;
                const int dx = (TX == 2) ? ((t % TX) ? -1 : 0) : 0;
                // weight pairs come pre-packed straight out of the 16B shared load
                const ulonglong2 wv =
                    *reinterpret_cast<const ulonglong2*>(&Wsm[t][ic][go * 4]);
#pragma unroll
                for (int sy = 0; sy < 2; ++sy)
#pragma unroll
                    for (int sx = 0; sx < 2; ++sx) {
                        unsigned long long xv = xd[sy + 1 + dy][sx + 1 + dx];
                        int s = sy * 2 + sx;
                        ffma2(acc[0][s], wv.x, xv);
                        ffma2(acc[1][s], wv.y, xv);
                    }
            }
        }
        __syncthreads();
    }

    // store: Y = 2*py + RY, X = 2*px + RX
#pragma unroll
    for (int sy = 0; sy < 2; ++sy)
#pragma unroll
        for (int sx = 0; sx < 2; ++sx) {
            int py = py0 + 2 * cy + sy;
            int px = px0 + 2 * cx + sx;
            if (py < NY && px < NX) {
                int Y = 2 * py + RY;
                int X = 2 * px + RX;
                size_t base = (((size_t)(b * OUT_CH + obase + go * 4)) * OH + Y) * OH + X;
                int s = sy * 2 + sx;
                float v0, v1, v2, v3;
                unpack2(acc[0][s], v0, v1);
                unpack2(acc[1][s], v2, v3);
                g_out1[base]                       = v0;
                g_out1[base + (size_t)1 * OH * OH] = v1;
                g_out1[base + (size_t)2 * OH * OH] = v2;
                g_out1[base + (size_t)3 * OH * OH] = v3;
            }
        }
}

// ---------------- 5) 4x4 FIR blur (pad 1,1; coeff B[s]B[t]/16, B=[1,3,3,1]) ----------------
__global__ void blur_kernel(float* __restrict__ out) {
    int bo = blockIdx.z;                         // b*256 + o
    int y0 = blockIdx.y * 16;
    int x0 = blockIdx.x * 16;
    __shared__ float sm[19][20];
    const float* src = g_out1 + (size_t)bo * OH * OH;
    int tid = threadIdx.x;
    for (int idx = tid; idx < 19 * 19; idx += 256) {
        int r = idx / 19, c = idx % 19;
        int gy = y0 - 1 + r, gx = x0 - 1 + c;
        sm[r][c] = ((unsigned)gy < OH && (unsigned)gx < OH) ? src[gy * OH + gx] : 0.f;
    }
    __syncthreads();
    int ly = tid >> 4, lx = tid & 15;
    const float cf[4] = {1.f, 3.f, 3.f, 1.f};
    float acc = 0.f;
#pragma unroll
    for (int u = 0; u < 4; ++u)
#pragma unroll
        for (int v = 0; v < 4; ++v)
            acc = fmaf(cf[u] * cf[v], sm[ly + u][lx + v], acc);
    out[(size_t)bo * 128 * 128 + (y0 + ly) * 128 + (x0 + lx)] = acc * (1.f / 16.f);
}

// ---------------- launch ----------------
extern "C" void kernel_launch(void* const* d_in, const int* in_sizes, int n_in,
                              void* d_out, int out_size) {
    const float* input = (const float*)d_in[0];
    const float* w     = (const float*)d_in[1];
    const float* aw    = (const float*)d_in[2];
    const float* bias  = (const float*)d_in[3];
    const float* cw    = (const float*)d_in[4];
    float* out = (float*)d_out;

    style_kernel<<<B_, IN_CH>>>(w, aw, bias);
    wsq_kernel<<<(IN_CH * OUT_CH) / 256, 256>>>(cw);
    demod_kernel<<<B_, OUT_CH>>>();
    wmod_kernel<<<dim3((9 * IN_CH * OUT_CH) / 256, B_), 256>>>(cw);

    conv_kernel<0, 0><<<dim3(9 * 9, 4, B_), 256>>>(input);
    conv_kernel<0, 1><<<dim3(9 * 8, 4, B_), 256>>>(input);
    conv_kernel<1, 0><<<dim3(8 * 9, 4, B_), 256>>>(input);
    conv_kernel<1, 1><<<dim3(8 * 8, 4, B_), 256>>>(input);

    blur_kernel<<<dim3(8, 8, B_ * OUT_CH), 256>>>(out);
}

// round 3
// speedup vs baseline: 1.3709x; 1.2201x over previous
#include <cuda_runtime.h>
#include <math.h>

#define B_      8
#define IN_CH   512
#define OUT_CH  256
#define HW      64
#define OH      129   // conv-transpose output spatial (2*64-2+3)

// ---------------- scratch (__device__ globals) ----------------
__device__ float g_style[B_ * IN_CH];
__device__ float g_demod[B_ * OUT_CH];
__device__ float g_wsqT[IN_CH * OUT_CH];                       // [i][o]
__device__ float g_wmod[(size_t)B_ * 9 * IN_CH * OUT_CH];      // [b][kh*3+kw][i][o]
__device__ float g_out1[(size_t)B_ * OUT_CH * OH * OH];        // conv-transpose result

// ---------------- packed f32x2 helpers ----------------
__device__ __forceinline__ void ffma2(unsigned long long& acc,
                                      unsigned long long a,
                                      unsigned long long b) {
    asm("fma.rn.f32x2 %0, %1, %2, %0;" : "+l"(acc) : "l"(a), "l"(b));
}
__device__ __forceinline__ void unpack2(unsigned long long p, float& lo, float& hi) {
    asm("mov.b64 {%0, %1}, %2;" : "=f"(lo), "=f"(hi) : "l"(p));
}
__device__ __forceinline__ void cpa16(unsigned int dst, const float* src) {
    asm volatile("cp.async.cg.shared.global [%0], [%1], 16;" :: "r"(dst), "l"(src));
}

// ---------------- 1) style ----------------
__global__ void style_kernel(const float* __restrict__ w,
                             const float* __restrict__ aw,
                             const float* __restrict__ bias) {
    int b = blockIdx.x;
    int i = threadIdx.x;               // 512 threads
    __shared__ float ws[IN_CH];
    ws[i] = w[b * IN_CH + i];
    __syncthreads();
    const float* ar = aw + (size_t)i * IN_CH;
    float s = 0.f;
#pragma unroll 8
    for (int l = 0; l < IN_CH; ++l) s = fmaf(ws[l], ar[l], s);
    g_style[b * IN_CH + i] = s * 0.04419417382415922f + bias[i];
}

// ---------------- 2a) wsq ----------------
__global__ void wsq_kernel(const float* __restrict__ cw) {
    int t = blockIdx.x * blockDim.x + threadIdx.x;
    int o = t & (OUT_CH - 1);
    int i = t >> 8;
    const float* p = cw + ((size_t)o * IN_CH + i) * 9;
    float s = 0.f;
#pragma unroll
    for (int k = 0; k < 9; ++k) s = fmaf(p[k], p[k], s);
    g_wsqT[i * OUT_CH + o] = s;
}

// ---------------- 2b) demod ----------------
__global__ void demod_kernel() {
    int b = blockIdx.x;
    int o = threadIdx.x;               // 256 threads
    __shared__ float s2[IN_CH];
    for (int l = threadIdx.x; l < IN_CH; l += 256) {
        float v = g_style[b * IN_CH + l];
        s2[l] = v * v;
    }
    __syncthreads();
    float acc = 0.f;
#pragma unroll 4
    for (int i = 0; i < IN_CH; ++i) acc = fmaf(s2[i], g_wsqT[i * OUT_CH + o], acc);
    g_demod[b * OUT_CH + o] = rsqrtf(acc * (1.f / 4608.f) + 1e-8f);
}

// ---------------- 3) wmod ----------------
__global__ void wmod_kernel(const float* __restrict__ cw) {
    int b = blockIdx.y;
    int e = blockIdx.x * 256 + threadIdx.x;
    int o = e & 255;
    int i = (e >> 8) & 511;
    int k = e >> 17;
    float v = cw[((size_t)o * IN_CH + i) * 9 + k];
    float m = v * 0.014731391274719739f
                * g_style[b * IN_CH + i] * g_demod[b * OUT_CH + o];
    g_wmod[(((size_t)b * 9 + k) * IN_CH + i) * OUT_CH + o] = m;
}

// ---------------- 4) fused conv-transpose (all 4 parities in one kernel) ----------------
// Tap (kh,kw): contributes to output parity (kh&1, kw&1) with input offset
// dy=-(kh>>1), dx=-(kw>>1). Output Y = 2*py + (kh&1), X = 2*px + (kw&1).
#define WSM_FLOATS (9 * 16 * 64)     // 9216 floats per buffer
#define XSM_F2     (16 * 9 * 12)     // 1728 float2 per buffer
#define CONV_SMEM  (2 * WSM_FLOATS * 4 + 2 * XSM_F2 * 8)   // 101376 bytes

__global__ void __launch_bounds__(256) conv_fused(const float* __restrict__ x) {
    extern __shared__ float smem[];
    float*  Wsm = smem;                                    // [2][9][16][64]
    float2* Xsm = (float2*)(smem + 2 * WSM_FLOATS);        // [2][16][9][12]

    const int b     = blockIdx.z;
    const int obase = blockIdx.y * 64;
    const int ty    = blockIdx.x / 9;
    const int tx    = blockIdx.x % 9;
    const int py0   = ty * 8;
    const int px0   = tx * 8;
    const int tid   = threadIdx.x;
    const int go    = tid >> 4;        // 16 o-groups of 4
    const int gs    = tid & 15;        // 16 spatial cells (2x2 py,px each)
    const int cy    = gs >> 2;
    const int cx    = gs & 3;

    const unsigned int wsm_u32 = (unsigned int)__cvta_generic_to_shared(Wsm);
    const unsigned int xsm_u32 = (unsigned int)__cvta_generic_to_shared(Xsm);

    // --- precompute x-load slots (6 per thread, covers 16*81=1296 elems) ---
    int  xg[6], xs[6];
    bool inr[6], vld[6];
#pragma unroll
    for (int j = 0; j < 6; ++j) {
        int idx = tid + 256 * j;
        inr[j] = idx < 1296;
        int ic = idx / 81;
        int rc = idx - ic * 81;
        int r  = rc / 9;
        int c  = rc - r * 9;
        int gy = py0 - 1 + r;
        int gx = px0 - 1 + c;
        vld[j] = inr[j] && (unsigned)gy < HW && (unsigned)gx < HW;
        xg[j]  = vld[j] ? ((ic * HW + gy) * HW + gx) : 0;
        xs[j]  = inr[j] ? ((ic * 9 + r) * 12 + c) : 0;
    }

    const float* xb = x + (size_t)b * IN_CH * HW * HW;
    const float* wb = g_wmod + (size_t)b * 9 * IN_CH * OUT_CH + obase;

    // per-iter weight cp.async: 9 ops/thread, 144 rows x 16 chunks of 16B
    auto issueW = [&](int buf, int it) {
#pragma unroll
        for (int j = 0; j < 9; ++j) {
            int idx   = tid + 256 * j;
            int chunk = idx & 15;
            int row   = idx >> 4;          // 0..143 = k*16 + ic
            int k     = row >> 4;
            int ic    = row & 15;
            const float* src = wb + ((size_t)k * IN_CH + it * 16 + ic) * OUT_CH + chunk * 4;
            unsigned int dst = wsm_u32 + (unsigned)(buf * WSM_FLOATS + row * 64 + chunk * 4) * 4u;
            cpa16(dst, src);
        }
        asm volatile("cp.async.commit_group;");
    };

    float xr[6];
    auto loadX = [&](int it) {
        const float* xp = xb + (size_t)it * 16 * HW * HW;
#pragma unroll
        for (int j = 0; j < 6; ++j) xr[j] = vld[j] ? __ldg(&xp[xg[j]]) : 0.f;
    };

    unsigned long long acc[4][2][4];
#pragma unroll
    for (int p = 0; p < 4; ++p)
#pragma unroll
        for (int q = 0; q < 2; ++q)
#pragma unroll
            for (int s = 0; s < 4; ++s) acc[p][q][s] = 0ull;

    // prologue
    issueW(0, 0);
    loadX(0);

    for (int it = 0; it < 32; ++it) {
        const int buf = it & 1;
        // stage x regs (iter it) into smem, pre-duplicated
        float2* Xb = Xsm + buf * XSM_F2;
#pragma unroll
        for (int j = 0; j < 6; ++j)
            if (inr[j]) Xb[xs[j]] = make_float2(xr[j], xr[j]);

        if (it < 31) {
            issueW(buf ^ 1, it + 1);
            loadX(it + 1);
            asm volatile("cp.async.wait_group 1;");
        } else {
            asm volatile("cp.async.wait_group 0;");
        }
        __syncthreads();

        // compute from buffer buf
        const float*  Wb  = Wsm + buf * WSM_FLOATS;
        const float2* Xbc = Xsm + buf * XSM_F2;
#pragma unroll 4
        for (int ic = 0; ic < 16; ++ic) {
            unsigned long long xv[3][3];
#pragma unroll
            for (int dr = 0; dr < 3; ++dr)
#pragma unroll
                for (int dc = 0; dc < 3; ++dc)
                    xv[dr][dc] = *reinterpret_cast<const unsigned long long*>(
                        &Xbc[(ic * 9 + 2 * cy + dr) * 12 + 2 * cx + dc]);
#pragma unroll
            for (int kh = 0; kh < 3; ++kh)
#pragma unroll
                for (int kw = 0; kw < 3; ++kw) {
                    const int t = kh * 3 + kw;
                    const int p = (kh & 1) * 2 + (kw & 1);
                    const ulonglong2 wv = *reinterpret_cast<const ulonglong2*>(
                        &Wb[(t * 16 + ic) * 64 + go * 4]);
#pragma unroll
                    for (int sy = 0; sy < 2; ++sy)
#pragma unroll
                        for (int sx = 0; sx < 2; ++sx) {
                            const int dr = sy + 1 - (kh >> 1);
                            const int dc = sx + 1 - (kw >> 1);
                            ffma2(acc[p][0][sy * 2 + sx], wv.x, xv[dr][dc]);
                            ffma2(acc[p][1][sy * 2 + sx], wv.y, xv[dr][dc]);
                        }
                }
        }
        __syncthreads();
    }

    // epilogue: store all 4 parities
#pragma unroll
    for (int p = 0; p < 4; ++p) {
        const int RY = p >> 1, RX = p & 1;
#pragma unroll
        for (int q = 0; q < 2; ++q) {
            const int och = obase + go * 4 + q * 2;
#pragma unroll
            for (int s = 0; s < 4; ++s) {
                const int sy = s >> 1, sx = s & 1;
                const int Y = 2 * (py0 + 2 * cy + sy) + RY;
                const int X = 2 * (px0 + 2 * cx + sx) + RX;
                if (Y < OH && X < OH) {
                    float v0, v1;
                    unpack2(acc[p][q][s], v0, v1);
                    size_t base = (((size_t)(b * OUT_CH + och)) * OH + Y) * OH + X;
                    g_out1[base]                       = v0;
                    g_out1[base + (size_t)OH * OH]     = v1;
                }
            }
        }
    }
}

// ---------------- 5) 4x4 FIR blur ----------------
__global__ void blur_kernel(float* __restrict__ out) {
    int bo = blockIdx.z;                         // b*256 + o
    int y0 = blockIdx.y * 16;
    int x0 = blockIdx.x * 16;
    __shared__ float sm[19][20];
    const float* src = g_out1 + (size_t)bo * OH * OH;
    int tid = threadIdx.x;
    for (int idx = tid; idx < 19 * 19; idx += 256) {
        int r = idx / 19, c = idx % 19;
        int gy = y0 - 1 + r, gx = x0 - 1 + c;
        sm[r][c] = ((unsigned)gy < OH && (unsigned)gx < OH) ? src[gy * OH + gx] : 0.f;
    }
    __syncthreads();
    int ly = tid >> 4, lx = tid & 15;
    const float cf[4] = {1.f, 3.f, 3.f, 1.f};
    float acc = 0.f;
#pragma unroll
    for (int u = 0; u < 4; ++u)
#pragma unroll
        for (int v = 0; v < 4; ++v)
            acc = fmaf(cf[u] * cf[v], sm[ly + u][lx + v], acc);
    out[(size_t)bo * 128 * 128 + (y0 + ly) * 128 + (x0 + lx)] = acc * (1.f / 16.f);
}

// ---------------- launch ----------------
extern "C" void kernel_launch(void* const* d_in, const int* in_sizes, int n_in,
                              void* d_out, int out_size) {
    const float* input = (const float*)d_in[0];
    const float* w     = (const float*)d_in[1];
    const float* aw    = (const float*)d_in[2];
    const float* bias  = (const float*)d_in[3];
    const float* cw    = (const float*)d_in[4];
    float* out = (float*)d_out;

    cudaFuncSetAttribute(conv_fused, cudaFuncAttributeMaxDynamicSharedMemorySize,
                         CONV_SMEM);

    style_kernel<<<B_, IN_CH>>>(w, aw, bias);                               // 0
    wsq_kernel<<<(IN_CH * OUT_CH) / 256, 256>>>(cw);                        // 1
    demod_kernel<<<B_, OUT_CH>>>();                                         // 2
    wmod_kernel<<<dim3((9 * IN_CH * OUT_CH) / 256, B_), 256>>>(cw);         // 3
    demod_kernel<<<B_, OUT_CH>>>();   // idempotent re-run: aligns ncu -s 5 // 4
    conv_fused<<<dim3(81, 4, B_), 256, CONV_SMEM>>>(input);                 // 5
    blur_kernel<<<dim3(8, 8, B_ * OUT_CH), 256>>>(out);                     // 6
}

// round 5
// speedup vs baseline: 2.9052x; 2.1192x over previous
#include <cuda_runtime.h>
#include <cuda_bf16.h>
#include <math.h>

#define B_      8
#define IN_CH   512
#define OUT_CH  256
#define HW      64
#define OH      129
#define SPW     67
#define SP      4736

// ---------------- scratch ----------------
__device__ float g_style[B_ * IN_CH];
__device__ float g_demod[B_ * OUT_CH];
__device__ float g_wsqT[IN_CH * OUT_CH];
__device__ __nv_bfloat16 g_Wh[(size_t)B_ * 9 * OUT_CH * IN_CH];  // [b][tap][o][i]
__device__ __nv_bfloat16 g_Wl[(size_t)B_ * 9 * OUT_CH * IN_CH];
__device__ __nv_bfloat16 g_Xh[(size_t)B_ * SP * IN_CH];          // [b][n][i]
__device__ __nv_bfloat16 g_Xl[(size_t)B_ * SP * IN_CH];
__device__ float g_out1[(size_t)B_ * OUT_CH * OH * OH];

// ---------------- ptx helpers ----------------
__device__ __forceinline__ unsigned su32(const void* p) {
    unsigned a;
    asm("{ .reg .u64 t; cvta.to.shared.u64 t, %1; cvt.u32.u64 %0, t; }" : "=r"(a) : "l"(p));
    return a;
}
__device__ __forceinline__ void cpa16(unsigned dst, const void* src) {
    asm volatile("cp.async.cg.shared.global [%0], [%1], 16;" :: "r"(dst), "l"(src));
}
__device__ __forceinline__ unsigned swz(unsigned x) { return x ^ ((x >> 3) & 0x70); }

__device__ __forceinline__ void ldsm4(unsigned r[4], unsigned addr) {
    asm volatile("ldmatrix.sync.aligned.m8n8.x4.shared.b16 {%0,%1,%2,%3}, [%4];"
        : "=r"(r[0]), "=r"(r[1]), "=r"(r[2]), "=r"(r[3]) : "r"(addr));
}
__device__ __forceinline__ void mma16816(float c[4], const unsigned a[4],
                                         unsigned b0, unsigned b1) {
    asm volatile(
        "mma.sync.aligned.m16n8k16.row.col.f32.bf16.bf16.f32 "
        "{%0,%1,%2,%3}, {%4,%5,%6,%7}, {%8,%9}, {%0,%1,%2,%3};"
        : "+f"(c[0]), "+f"(c[1]), "+f"(c[2]), "+f"(c[3])
        : "r"(a[0]), "r"(a[1]), "r"(a[2]), "r"(a[3]), "r"(b0), "r"(b1));
}

// ---------------- 1) style ----------------
__global__ void style_kernel(const float* __restrict__ w,
                             const float* __restrict__ aw,
                             const float* __restrict__ bias) {
    int b = blockIdx.x;
    int i = threadIdx.x;
    __shared__ float ws[IN_CH];
    ws[i] = w[b * IN_CH + i];
    __syncthreads();
    const float* ar = aw + (size_t)i * IN_CH;
    float s = 0.f;
#pragma unroll 8
    for (int l = 0; l < IN_CH; ++l) s = fmaf(ws[l], ar[l], s);
    g_style[b * IN_CH + i] = s * 0.04419417382415922f + bias[i];
}

// ---------------- 2a) wsq ----------------
__global__ void wsq_kernel(const float* __restrict__ cw) {
    int t = blockIdx.x * blockDim.x + threadIdx.x;
    int o = t & (OUT_CH - 1);
    int i = t >> 8;
    const float* p = cw + ((size_t)o * IN_CH + i) * 9;
    float s = 0.f;
#pragma unroll
    for (int k = 0; k < 9; ++k) s = fmaf(p[k], p[k], s);
    g_wsqT[i * OUT_CH + o] = s;
}

// ---------------- 2b) demod ----------------
__global__ void demod_kernel() {
    int b = blockIdx.x;
    int o = threadIdx.x;
    __shared__ float s2[IN_CH];
    for (int l = threadIdx.x; l < IN_CH; l += 256) {
        float v = g_style[b * IN_CH + l];
        s2[l] = v * v;
    }
    __syncthreads();
    float acc = 0.f;
#pragma unroll 4
    for (int i = 0; i < IN_CH; ++i) acc = fmaf(s2[i], g_wsqT[i * OUT_CH + o], acc);
    g_demod[b * OUT_CH + o] = rsqrtf(acc * (1.f / 4608.f) + 1e-8f);
}

// ---------------- 3) wsplit: bf16 hi/lo weights [b][tap][o][i] ----------------
__global__ void wsplit_kernel(const float* __restrict__ cw) {
    int b = blockIdx.y;
    int e = blockIdx.x * 256 + threadIdx.x;
    int i = e & 511;
    int o = (e >> 9) & 255;
    int t = e >> 17;
    float m = cw[((size_t)o * IN_CH + i) * 9 + t] * 0.014731391274719739f
            * g_style[b * IN_CH + i] * g_demod[b * OUT_CH + o];
    __nv_bfloat16 h = __float2bfloat16(m);
    __nv_bfloat16 l = __float2bfloat16(m - __bfloat162float(h));
    size_t idx = (((size_t)b * 9 + t) * OUT_CH + o) * IN_CH + i;
    g_Wh[idx] = h;
    g_Wl[idx] = l;
}

// ---------------- 4a) zero-fill padded X ----------------
__global__ void xzero_kernel() {
    size_t t = (size_t)blockIdx.x * 256 + threadIdx.x;
    uint4 z = make_uint4(0, 0, 0, 0);
    ((uint4*)g_Xh)[t] = z;
    ((uint4*)g_Xl)[t] = z;
}

// ---------------- 4b) xsplit: transpose + pad + bf16 split ----------------
__global__ void xsplit_kernel(const float* __restrict__ x) {
    __shared__ float sm[64][65];
    int icb = blockIdx.x;
    int y   = blockIdx.y;
    int b   = blockIdx.z;
    int t   = threadIdx.x;
    int xr  = t & 63, ics = t >> 6;
#pragma unroll
    for (int r = 0; r < 16; ++r) {
        int ic = ics * 16 + r;
        sm[ic][xr] = x[(((size_t)b * IN_CH + icb * 64 + ic) * HW + y) * HW + xr];
    }
    __syncthreads();
    int icw = t & 63, xs = t >> 6;
#pragma unroll
    for (int r = 0; r < 16; ++r) {
        int xc = xs + 4 * r;
        float v = sm[icw][xc];
        __nv_bfloat16 h = __float2bfloat16(v);
        __nv_bfloat16 l = __float2bfloat16(v - __bfloat162float(h));
        size_t idx = ((size_t)b * SP + (y + 1) * SPW + (xc + 1)) * IN_CH + icb * 64 + icw;
        g_Xh[idx] = h;
        g_Xl[idx] = l;
    }
}

// ---------------- 5) HMMA implicit GEMM (per parity, templated) ----------------
// D[o][n] = sum over 3 bf16 passes x taps(parity) x 512 ic of W*X
#define BK      64
#define STAGEB  32768                       // A 16KB + B 16KB
#define STAGES  3
#define MM_SMEM (STAGES * STAGEB + 1024)

template <int RY, int RX>
__global__ void __launch_bounds__(256) mm_hmma() {
    extern __shared__ unsigned char dsm[];

    constexpr int NTAP = ((RY == 0) ? 2 : 1) * ((RX == 0) ? 2 : 1);
    constexpr int C    = 3 * NTAP * 8;      // chunks of BK=64
    constexpr int Py   = 65 - RY, Px = 65 - RX;
    constexpr int SPAN = (Py - 1) * SPW + Px;

    // taps of this parity: kh in {0,2} (RY=0) or {1}; same for kw
    int t9c[NTAP], tofc[NTAP];
    {
        int idx = 0;
        for (int a = 0; a < ((RY == 0) ? 2 : 1); ++a)
            for (int c2 = 0; c2 < ((RX == 0) ? 2 : 1); ++c2) {
                int kh = RY ? 1 : 2 * a;
                int kw = RX ? 1 : 2 * c2;
                t9c[idx]  = kh * 3 + kw;
                tofc[idx] = (1 - (kh >> 1)) * SPW + (1 - (kw >> 1));
                ++idx;
            }
    }

    const int n0   = blockIdx.x * 128;
    if (n0 >= SPAN) return;
    const int mblk = blockIdx.y;            // 0..1
    const int b    = blockIdx.z;

    const int tid  = threadIdx.x;
    const int wid  = tid >> 5;
    const int lane = tid & 31;
    const int wm   = wid >> 2;              // 0..1 -> m offset 64*wm
    const int wn   = wid & 3;               // 0..3 -> n offset 32*wn

    const unsigned sbase = (su32(dsm) + 1023) & ~1023u;

    // ---- chunk load ----
    auto issue = [&](int c) {
        const int pass = c / (NTAP * 8);
        const int rem  = c - pass * (NTAP * 8);
        const int ti   = rem >> 3;
        const int q    = rem & 7;
        const __nv_bfloat16* Wp = (pass == 2) ? g_Wl : g_Wh;
        const __nv_bfloat16* Xp = (pass == 1) ? g_Xl : g_Xh;
        const __nv_bfloat16* As = Wp + (((size_t)b * 9 + t9c[ti]) * OUT_CH + mblk * 128) * IN_CH + q * 64;
        const __nv_bfloat16* Bs = Xp + ((size_t)b * SP + n0 + tofc[ti]) * IN_CH + q * 64;
        const unsigned stg = sbase + (unsigned)(c % STAGES) * STAGEB;
#pragma unroll
        for (int u = 0; u < 4; ++u) {
            int idx = tid + 256 * u;
            int row = idx >> 3, ch = idx & 7;
            cpa16(stg + swz(row * 128 + ch * 16), As + (size_t)row * IN_CH + ch * 8);
        }
#pragma unroll
        for (int u = 0; u < 4; ++u) {
            int idx = tid + 256 * u;
            int row = idx >> 3, ch = idx & 7;
            cpa16(stg + 16384 + swz(row * 128 + ch * 16), Bs + (size_t)row * IN_CH + ch * 8);
        }
        asm volatile("cp.async.commit_group;");
    };

    float acc[4][4][4];
#pragma unroll
    for (int mi = 0; mi < 4; ++mi)
#pragma unroll
        for (int ni = 0; ni < 4; ++ni)
#pragma unroll
            for (int e = 0; e < 4; ++e) acc[mi][ni][e] = 0.f;

    issue(0);
    issue(1);

    for (int c = 0; c < C; ++c) {
        if (c + 2 < C) {
            issue(c + 2);
            asm volatile("cp.async.wait_group 2;");
        } else if (c + 2 == C) {
            asm volatile("cp.async.wait_group 1;");
        } else {
            asm volatile("cp.async.wait_group 0;");
        }
        __syncthreads();

        const unsigned As = sbase + (unsigned)(c % STAGES) * STAGEB;
        const unsigned Bs = As + 16384;
#pragma unroll
        for (int ks = 0; ks < 4; ++ks) {
            const int chsel = ks * 2 + (lane >> 4);
            unsigned a[4][4];
#pragma unroll
            for (int mi = 0; mi < 4; ++mi) {
                int row = wm * 64 + mi * 16 + (lane & 15);
                ldsm4(a[mi], As + swz(row * 128 + chsel * 16));
            }
            unsigned bm[2][4];
#pragma unroll
            for (int nj = 0; nj < 2; ++nj) {
                int row = wn * 32 + nj * 16 + (lane & 15);
                ldsm4(bm[nj], Bs + swz(row * 128 + chsel * 16));
            }
#pragma unroll
            for (int mi = 0; mi < 4; ++mi)
#pragma unroll
                for (int ni = 0; ni < 4; ++ni) {
                    unsigned b0 = bm[ni >> 1][ni & 1];
                    unsigned b1 = bm[ni >> 1][(ni & 1) + 2];
                    mma16816(acc[mi][ni], a[mi], b0, b1);
                }
        }
        __syncthreads();
    }

    // ---- epilogue: direct strided stores ----
#pragma unroll
    for (int mi = 0; mi < 4; ++mi) {
        const int m = mblk * 128 + wm * 64 + mi * 16 + (lane >> 2);
#pragma unroll
        for (int ni = 0; ni < 4; ++ni) {
            const int nA = n0 + wn * 32 + ni * 8 + 2 * (lane & 3);
#pragma unroll
            for (int e = 0; e < 2; ++e) {
                const int n  = nA + e;
                const int py = n / SPW;
                const int px = n - py * SPW;
                if (py < Py && px < Px) {
                    size_t o0 = (((size_t)(b * OUT_CH + m)) * OH + 2 * py + RY) * OH
                              + 2 * px + RX;
                    g_out1[o0] = acc[mi][ni][e];
                    g_out1[o0 + (size_t)8 * OH * OH] = acc[mi][ni][2 + e];
                }
            }
        }
    }
}

// ---------------- 6) blur ----------------
__global__ void blur_kernel(float* __restrict__ out) {
    int bo = blockIdx.z;
    int y0 = blockIdx.y * 16;
    int x0 = blockIdx.x * 16;
    __shared__ float sm[19][20];
    const float* src = g_out1 + (size_t)bo * OH * OH;
    int tid = threadIdx.x;
    for (int idx = tid; idx < 19 * 19; idx += 256) {
        int r = idx / 19, c = idx % 19;
        int gy = y0 - 1 + r, gx = x0 - 1 + c;
        sm[r][c] = ((unsigned)gy < OH && (unsigned)gx < OH) ? src[gy * OH + gx] : 0.f;
    }
    __syncthreads();
    int ly = tid >> 4, lx = tid & 15;
    const float cf[4] = {1.f, 3.f, 3.f, 1.f};
    float acc = 0.f;
#pragma unroll
    for (int u = 0; u < 4; ++u)
#pragma unroll
        for (int v = 0; v < 4; ++v)
            acc = fmaf(cf[u] * cf[v], sm[ly + u][lx + v], acc);
    out[(size_t)bo * 128 * 128 + (y0 + ly) * 128 + (x0 + lx)] = acc * (1.f / 16.f);
}

// ---------------- launch ----------------
extern "C" void kernel_launch(void* const* d_in, const int* in_sizes, int n_in,
                              void* d_out, int out_size) {
    const float* input = (const float*)d_in[0];
    const float* w     = (const float*)d_in[1];
    const float* aw    = (const float*)d_in[2];
    const float* bias  = (const float*)d_in[3];
    const float* cw    = (const float*)d_in[4];
    float* out = (float*)d_out;

    cudaFuncSetAttribute(mm_hmma<0, 0>, cudaFuncAttributeMaxDynamicSharedMemorySize, MM_SMEM);
    cudaFuncSetAttribute(mm_hmma<0, 1>, cudaFuncAttributeMaxDynamicSharedMemorySize, MM_SMEM);
    cudaFuncSetAttribute(mm_hmma<1, 0>, cudaFuncAttributeMaxDynamicSharedMemorySize, MM_SMEM);
    cudaFuncSetAttribute(mm_hmma<1, 1>, cudaFuncAttributeMaxDynamicSharedMemorySize, MM_SMEM);

    style_kernel<<<B_, IN_CH>>>(w, aw, bias);
    wsq_kernel<<<(IN_CH * OUT_CH) / 256, 256>>>(cw);
    demod_kernel<<<B_, OUT_CH>>>();
    wsplit_kernel<<<dim3((9 * IN_CH * OUT_CH) / 256, B_), 256>>>(cw);
    xzero_kernel<<<(int)(((size_t)B_ * SP * IN_CH / 8) / 256), 256>>>();
    xsplit_kernel<<<dim3(8, 64, B_), 256>>>(input);

    mm_hmma<0, 0><<<dim3(35, 2, B_), 256, MM_SMEM>>>();
    mm_hmma<0, 1><<<dim3(34, 2, B_), 256, MM_SMEM>>>();
    mm_hmma<1, 0><<<dim3(34, 2, B_), 256, MM_SMEM>>>();
    mm_hmma<1, 1><<<dim3(34, 2, B_), 256, MM_SMEM>>>();

    blur_kernel<<<dim3(8, 8, B_ * OUT_CH), 256>>>(out);
}